// round 14
// baseline (speedup 1.0000x reference)
#include <cuda_runtime.h>
#include <cuda_fp16.h>
#include <cstdint>

#define B_   16
#define IC_  128
#define OC_  128
#define SD_  512
#define H_   128
#define W_   128
#define HW_  (H_*W_)   // 16384

#define CONV_SCALE 0.029462782549439476f   // 1/sqrt(1152)
#define LIN_SCALE  0.044194173824159216f   // 1/sqrt(512)

// ---------------- device scratch (no allocation allowed) -------------------
__device__ float  g_s[B_ * IC_];                          // modulation s[b][ic]
__device__ __half g_wh[(size_t)B_ * 9 * OC_ * IC_];       // [b][tap][oc][ic] fp16
__device__ __half g_ch[(size_t)B_ * HW_ * IC_];           // [b][pixel][ic] fp16 channels-last

// ---------------- helpers ---------------------------------------------------
__device__ __forceinline__ uint32_t s2u(const void* p) {
    uint32_t a;
    asm("{ .reg .u64 t; cvta.to.shared.u64 t, %1; cvt.u32.u64 %0, t; }" : "=r"(a) : "l"(p));
    return a;
}
__device__ __forceinline__ void cpa16(uint32_t dst, const void* src, int sz) {
    asm volatile("cp.async.cg.shared.global [%0], [%1], 16, %2;"
                 :: "r"(dst), "l"(src), "r"(sz) : "memory");
}
__device__ __forceinline__ void ldsm_x4(uint32_t a, uint32_t& r0, uint32_t& r1,
                                        uint32_t& r2, uint32_t& r3) {
    asm volatile("ldmatrix.sync.aligned.m8n8.x4.shared.b16 {%0,%1,%2,%3}, [%4];"
                 : "=r"(r0), "=r"(r1), "=r"(r2), "=r"(r3) : "r"(a));
}
__device__ __forceinline__ void hmma(float& c0, float& c1, float& c2, float& c3,
                                     uint32_t a0, uint32_t a1, uint32_t a2, uint32_t a3,
                                     uint32_t b0, uint32_t b1) {
    asm volatile(
        "mma.sync.aligned.m16n8k16.row.col.f32.f16.f16.f32 "
        "{%0,%1,%2,%3}, {%4,%5,%6,%7}, {%8,%9}, {%0,%1,%2,%3};"
        : "+f"(c0), "+f"(c1), "+f"(c2), "+f"(c3)
        : "r"(a0), "r"(a1), "r"(a2), "r"(a3), "r"(b0), "r"(b1));
}

// ---------------------------------------------------------------------------
// Kernel 1: s[b][ic] = dot(style[b], mod_w[ic]) * lin_scale + mod_b[ic]
// ---------------------------------------------------------------------------
__global__ void mod_kernel(const float* __restrict__ style,
                           const float* __restrict__ mod_w,
                           const float* __restrict__ mod_b) {
    int warp = threadIdx.x >> 5, lane = threadIdx.x & 31;
    int idx  = blockIdx.x * 4 + warp;
    int b = idx >> 7, ic = idx & 127;
    const float* st = style + b * SD_;
    const float* mw = mod_w + ic * SD_;
    float sum = 0.f;
    #pragma unroll 4
    for (int j = lane; j < SD_; j += 32) sum += st[j] * mw[j];
    #pragma unroll
    for (int o = 16; o; o >>= 1) sum += __shfl_xor_sync(0xffffffffu, sum, o);
    if (lane == 0) g_s[idx] = sum * LIN_SCALE + mod_b[ic];
}

// ---------------------------------------------------------------------------
// Kernel 2: demodulate, write fp16 weights g_wh[b][tap][oc][ic].
// ---------------------------------------------------------------------------
__global__ void demod_kernel(const float* __restrict__ weight) {
    __shared__ float ws[IC_ * 9];
    int oc = blockIdx.x, b = blockIdx.y, ic = threadIdx.x;
    const float* wbase = weight + (size_t)oc * IC_ * 9;
    for (int i = ic; i < IC_ * 9; i += 128) ws[i] = wbase[i];
    float s = g_s[b * IC_ + ic];
    __syncthreads();

    float v[9], ss = 0.f;
    #pragma unroll
    for (int k = 0; k < 9; ++k) { v[k] = CONV_SCALE * ws[ic * 9 + k] * s; ss += v[k] * v[k]; }
    #pragma unroll
    for (int o = 16; o; o >>= 1) ss += __shfl_xor_sync(0xffffffffu, ss, o);
    __shared__ float red[4];
    if ((threadIdx.x & 31) == 0) red[threadIdx.x >> 5] = ss;
    __syncthreads();
    float demod = rsqrtf(red[0] + red[1] + red[2] + red[3] + 1e-8f);
    #pragma unroll
    for (int k = 0; k < 9; ++k)
        g_wh[((size_t)(b * 9 + k) * OC_ + oc) * IC_ + ic] = __float2half(v[k] * demod);
}

// ---------------------------------------------------------------------------
// Kernel 3: content -> fp16 channels-last
// ---------------------------------------------------------------------------
__global__ void prep_content(const float* __restrict__ content) {
    __shared__ __half sm[128][130];
    int y = blockIdx.x, b = blockIdx.y, tid = threadIdx.x;
    const float* src = content + (size_t)b * IC_ * HW_ + y * W_;
    for (int i = tid; i < IC_ * W_ / 4; i += 256) {
        int ic = i >> 5, x0 = (i & 31) * 4;
        float4 v = *reinterpret_cast<const float4*>(src + (size_t)ic * HW_ + x0);
        sm[x0 + 0][ic] = __float2half(v.x);
        sm[x0 + 1][ic] = __float2half(v.y);
        sm[x0 + 2][ic] = __float2half(v.z);
        sm[x0 + 3][ic] = __float2half(v.w);
    }
    __syncthreads();
    uint2* dst = (uint2*)(g_ch + ((size_t)b * HW_ + (size_t)y * W_) * IC_);
    for (int i = tid; i < IC_ * W_ / 4; i += 256) {
        int x = i >> 5, icq = (i & 31) * 4;
        __half2 h0 = __halves2half2(sm[x][icq], sm[x][icq + 1]);
        __half2 h1 = __halves2half2(sm[x][icq + 2], sm[x][icq + 3]);
        uint2 u;
        u.x = *reinterpret_cast<uint32_t*>(&h0);
        u.y = *reinterpret_cast<uint32_t*>(&h1);
        dst[(size_t)x * 32 + (icq >> 2)] = u;
    }
}

// ---------------------------------------------------------------------------
// Kernel 4: implicit GEMM conv (HMMA) with RESIDENT B.
// CTA = (row y, sample b): D[128 oc][128 px], K = 2 ic-chunks x 9 taps x 64.
// Per chunk: B = 3 content rows (y-1,y,y+1) x [130 px pad] x 64 ic loaded ONCE
// (48.75KB, edges zero-filled); 9 taps read it at row x+dx, sub-buffer dy.
// A = per-tap [128 oc][64 ic] 16KB, 3-buffer cp.async ring, 1 sync/tap.
// SMEM: A ring 48KB + B 48.75KB = 99,072B -> 2 CTAs/SM.
// ---------------------------------------------------------------------------
#define SM_A_RING 49152u               // 3 x 16384
#define SM_B_SUB  16640u               // 130 rows x 128B
#define SM_TOTAL  (SM_A_RING + 3 * SM_B_SUB)   // 99,072

__global__ void __launch_bounds__(256, 2) conv_mma(float* __restrict__ out) {
    extern __shared__ char smem[];
    const uint32_t sb  = s2u(smem);          // A ring
    const uint32_t sbB = sb + SM_A_RING;     // B resident (3 sub-buffers)
    const int tid = threadIdx.x, wid = tid >> 5, lane = tid & 31;
    const int y = blockIdx.x, b = blockIdx.y;
    const int warp_m = wid & 3, warp_n = wid >> 2;

    // hoisted fragment-address terms
    uint32_t rowA[2], swA[2], xn[4];
    const uint32_t inA = (uint32_t)(lane >> 4) * 16u;
    const uint32_t inB = (uint32_t)((lane >> 3) & 1) * 16u;
    #pragma unroll
    for (int mt = 0; mt < 2; ++mt) {
        uint32_t row = warp_m * 32 + mt * 16 + (lane & 15);
        rowA[mt] = row * 128u;
        swA[mt]  = (row & 7u) << 4;
    }
    #pragma unroll
    for (int ntp = 0; ntp < 4; ++ntp)
        xn[ntp] = warp_n * 64 + ntp * 16 + ((lane >> 4) << 3) + (lane & 7);

    float acc[2][8][4];
    #pragma unroll
    for (int mt = 0; mt < 2; ++mt)
        #pragma unroll
        for (int nt = 0; nt < 8; ++nt)
            #pragma unroll
            for (int c = 0; c < 4; ++c) acc[mt][nt][c] = 0.f;

    auto issueA = [&](int tap, int chunk, uint32_t base) {
        const char* asrc = (const char*)g_wh
            + ((size_t)(b * 9 + tap) * OC_ * IC_ + chunk * 64) * 2;
        #pragma unroll
        for (int j = 0; j < 4; ++j) {
            int i = tid + j * 256;
            int row = i >> 3, c16 = i & 7;
            uint32_t off = (uint32_t)(row * 128 + c16 * 16);
            cpa16(base + (off ^ (((uint32_t)row & 7u) << 4)),
                  asrc + (size_t)row * IC_ * 2 + c16 * 16, 16);
        }
        asm volatile("cp.async.commit_group;" ::: "memory");
    };
    auto issueB = [&](int chunk) {
        #pragma unroll 1
        for (int i = tid; i < 3 * 130 * 8; i += 256) {
            int sub = i / 1040;                 // dy + 1
            int rem = i - sub * 1040;
            int r = rem >> 3, c16 = rem & 7;    // r = pixel+1
            int yy = y + sub - 1, p = r - 1;
            int ok = (yy >= 0 && yy < H_ && p >= 0 && p < W_) ? 16 : 0;
            size_t pix = (size_t)(ok ? yy : 0) * W_ + (ok ? p : 0);
            uint32_t off = (uint32_t)(r * 128 + c16 * 16);
            cpa16(sbB + (uint32_t)sub * SM_B_SUB + (off ^ (((uint32_t)r & 7u) << 4)),
                  (const char*)(g_ch + ((size_t)b * HW_ + pix) * IC_ + chunk * 64)
                      + c16 * 16, ok);
        }
        asm volatile("cp.async.commit_group;" ::: "memory");
    };

    #pragma unroll 1
    for (int c = 0; c < 2; ++c) {
        __syncthreads();                 // prior chunk fully consumed (B + A bufs)
        issueB(c);
        issueA(0, c, sb);
        issueA(1, c, sb + 16384u);

        int dy = -1, dx = 0, abuf = 0, nbuf = 2;
        #pragma unroll 1
        for (int t = 0; t < 9; ++t) {
            if (t < 8) asm volatile("cp.async.wait_group 1;" ::: "memory");
            else       asm volatile("cp.async.wait_group 0;" ::: "memory");
            __syncthreads();             // A buf nbuf free (last read at t-1)
            if (t + 2 < 9) issueA(t + 2, c, sb + (uint32_t)nbuf * 16384u);

            const uint32_t Abase = sb + (uint32_t)abuf * 16384u;
            const uint32_t Bdy   = sbB + (uint32_t)(dy + 1) * SM_B_SUB;
            abuf = (abuf == 2) ? 0 : abuf + 1;
            nbuf = (nbuf == 2) ? 0 : nbuf + 1;

            uint32_t rowB[4], swB[4];
            #pragma unroll
            for (int ntp = 0; ntp < 4; ++ntp) {
                uint32_t row = xn[ntp] + (uint32_t)dx;   // smem row = x + dx
                rowB[ntp] = row * 128u;
                swB[ntp]  = (row & 7u) << 4;
            }

            #pragma unroll
            for (int kst = 0; kst < 4; ++kst) {
                const uint32_t kadd = (uint32_t)kst * 32u;
                uint32_t a[2][4];
                #pragma unroll
                for (int mt = 0; mt < 2; ++mt)
                    ldsm_x4(Abase + rowA[mt] + ((inA + kadd) ^ swA[mt]),
                            a[mt][0], a[mt][1], a[mt][2], a[mt][3]);
                uint32_t bf[8][2];
                #pragma unroll
                for (int ntp = 0; ntp < 4; ++ntp)
                    ldsm_x4(Bdy + rowB[ntp] + ((inB + kadd) ^ swB[ntp]),
                            bf[2 * ntp][0], bf[2 * ntp][1],
                            bf[2 * ntp + 1][0], bf[2 * ntp + 1][1]);
                #pragma unroll
                for (int mt = 0; mt < 2; ++mt)
                    #pragma unroll
                    for (int nt = 0; nt < 8; ++nt)
                        hmma(acc[mt][nt][0], acc[mt][nt][1], acc[mt][nt][2], acc[mt][nt][3],
                             a[mt][0], a[mt][1], a[mt][2], a[mt][3],
                             bf[nt][0], bf[nt][1]);
            }
            if (++dx == 3) { dx = 0; ++dy; }
        }
    }

    // ---- epilogue ----
    const int qm = lane >> 2, qn = (lane & 3) * 2;
    #pragma unroll
    for (int mt = 0; mt < 2; ++mt) {
        #pragma unroll
        for (int nt = 0; nt < 8; ++nt) {
            int oc0 = warp_m * 32 + mt * 16 + qm;
            int px  = warp_n * 64 + nt * 8 + qn;
            float* d0 = out + ((size_t)(b * OC_ + oc0)) * HW_ + (size_t)y * W_ + px;
            *reinterpret_cast<float2*>(d0) =
                make_float2(acc[mt][nt][0], acc[mt][nt][1]);
            *reinterpret_cast<float2*>(d0 + 8 * HW_) =
                make_float2(acc[mt][nt][2], acc[mt][nt][3]);
        }
    }
}

// ---------------------------------------------------------------------------
extern "C" void kernel_launch(void* const* d_in, const int* in_sizes, int n_in,
                              void* d_out, int out_size) {
    const float* content = (const float*)d_in[0];
    const float* style   = (const float*)d_in[1];
    const float* weight  = (const float*)d_in[2];
    const float* mod_w   = (const float*)d_in[3];
    const float* mod_b   = (const float*)d_in[4];
    float* out = (float*)d_out;

    cudaFuncSetAttribute(conv_mma, cudaFuncAttributeMaxDynamicSharedMemorySize, SM_TOTAL);

    mod_kernel<<<512, 128>>>(style, mod_w, mod_b);
    demod_kernel<<<dim3(OC_, B_), 128>>>(weight);
    prep_content<<<dim3(H_, B_), 256>>>(content);
    conv_mma<<<dim3(H_, B_), 256, SM_TOTAL>>>(out);
}